// round 5
// baseline (speedup 1.0000x reference)
#include <cuda_runtime.h>
#include <cstdint>

#define T_LEN   512
#define BATCH   2048
#define NB      16
#define HID     64
#define NGATE   256
#define THREADS 512          // 16 warps: warp = 16-row slice x 16 batches
#define WP      68           // w_sh row stride: start bank 4r, conflict-free LDS.128
#define HP      68           // h_sh row stride: start bank 4b
#define GP      264          // gbuf row stride: bank 8b + col, conflict-free STS/LDS
#define XP      65           // x_sh row stride

typedef unsigned long long ull;

__device__ __forceinline__ uint32_t smem_u32(const void* p) {
    uint32_t a;
    asm("{ .reg .u64 t; cvta.to.shared.u64 t, %1; cvt.u32.u64 %0, t; }"
        : "=r"(a) : "l"(p));
    return a;
}
// 16B shared load straight into two b64 regs (no pack MOVs)
__device__ __forceinline__ void lds_v2u64(ull& a, ull& b, uint32_t addr) {
    asm volatile("ld.shared.v2.u64 {%0, %1}, [%2];"
                 : "=l"(a), "=l"(b) : "r"(addr));
}
__device__ __forceinline__ ull pack2(float x, float y) {
    ull r; asm("mov.b64 %0, {%1, %2};" : "=l"(r) : "f"(x), "f"(y)); return r;
}
__device__ __forceinline__ void unpack2(ull v, float& x, float& y) {
    asm("mov.b64 {%0, %1}, %2;" : "=f"(x), "=f"(y) : "l"(v));
}
// Packed f32x2 FMA (sm_10x FFMA2) — IEEE fp32 per lane, 2x FFMA throughput.
__device__ __forceinline__ ull fma2(ull a, ull b, ull c) {
    ull d; asm("fma.rn.f32x2 %0, %1, %2, %3;" : "=l"(d) : "l"(a), "l"(b), "l"(c));
    return d;
}
// MUFU tanh (1 MUFU op vs 2 for exp-based)
__device__ __forceinline__ float tanh_mufu(float x) {
    float r; asm("tanh.approx.f32 %0, %1;" : "=f"(r) : "f"(x)); return r;
}
// sigmoid(x) = 0.5*tanh(0.5x) + 0.5  (1 MUFU)
__device__ __forceinline__ float sigm(float x) {
    return fmaf(tanh_mufu(0.5f * x), 0.5f, 0.5f);
}

__global__ __launch_bounds__(THREADS, 1)
void lstm_kernel(const float* __restrict__ x,
                 const float* __restrict__ w_ih,
                 const float* __restrict__ w_hh,
                 const float* __restrict__ b_ih,
                 const float* __restrict__ b_hh,
                 const float* __restrict__ w_fc,
                 const float* __restrict__ b_fc,
                 float* __restrict__ out)
{
    extern __shared__ float smem[];
    float* w_sh = smem;                       // [NGATE][WP]  69632 B
    float* h_sh = w_sh + NGATE * WP;          // [NB][HP]      4352 B
    float* gbuf = h_sh + NB * HP;             // [NB][GP]     16896 B
    float* x_sh = gbuf + NB * GP;             // [NB][XP]      4160 B

    const int tid  = threadIdx.x;
    const int lane = tid & 31;
    const int warp = tid >> 5;                // 0..15: row slice warp*16..+15
    const int rg   = lane & 7;                // row offset within 8-group
    const int bl   = lane >> 3;               // batch lane group 0..3
    const int b0   = blockIdx.x * NB;

    // ---- stage w_hh into padded shared; zero h; stage x chunk 0 ----
    for (int idx = tid; idx < NGATE * HID; idx += THREADS) {
        int r = idx >> 6, k = idx & 63;
        w_sh[r * WP + k] = w_hh[idx];
    }
    for (int idx = tid; idx < NB * HP; idx += THREADS) h_sh[idx] = 0.0f;
    for (int idx = tid; idx < NB * HID; idx += THREADS) {
        int b = idx >> 6, t2 = idx & 63;
        x_sh[b * XP + t2] = x[(size_t)(b0 + b) * T_LEN + t2];
    }

    // ---- matvec identity: rows r_j = warp*16+rg+8j (j=0,1), batches bl+4i ----
    float wih[2], bias[2];
    uint32_t waddr[2], haddr[4];
    const uint32_t wbase = smem_u32(w_sh);
    const uint32_t hbase = smem_u32(h_sh);
    #pragma unroll
    for (int j = 0; j < 2; ++j) {
        int r = warp * 16 + rg + 8 * j;
        wih[j]   = w_ih[r];                   // I == 1
        bias[j]  = b_ih[r] + b_hh[r];
        waddr[j] = wbase + (uint32_t)(r * WP) * 4u;
    }
    #pragma unroll
    for (int i = 0; i < 4; ++i)
        haddr[i] = hbase + (uint32_t)((bl + 4 * i) * HP) * 4u;

    // ---- update identity: warp = batch, units lane and lane+32 ----
    float wfc0 = w_fc[lane], wfc1 = w_fc[lane + 32];
    float c0 = 0.0f, c1 = 0.0f;
    const float bfc = b_fc[0];

    __syncthreads();

    for (int t = 0; t < T_LEN; ++t) {
        const int tt = t & 63;

        // ---- matvec phase: acc[j][i] = gates(row j, batch i), f32x2 over k ----
        ull acc[2][4];
        #pragma unroll
        for (int i = 0; i < 4; ++i) {
            float xv = x_sh[(bl + 4 * i) * XP + tt];
            #pragma unroll
            for (int j = 0; j < 2; ++j)
                acc[j][i] = pack2(fmaf(xv, wih[j], bias[j]), 0.0f);
        }

        ull chlo[4], chhi[4], cwlo[2], cwhi[2];
        #pragma unroll
        for (int i = 0; i < 4; ++i) lds_v2u64(chlo[i], chhi[i], haddr[i]);
        #pragma unroll
        for (int j = 0; j < 2; ++j) lds_v2u64(cwlo[j], cwhi[j], waddr[j]);

        #pragma unroll
        for (int kc = 0; kc < 16; ++kc) {
            ull nhlo[4], nhhi[4], nwlo[2], nwhi[2];
            if (kc < 15) {                      // prefetch next chunk
                const uint32_t off = 16u * (uint32_t)(kc + 1);
                #pragma unroll
                for (int i = 0; i < 4; ++i) lds_v2u64(nhlo[i], nhhi[i], haddr[i] + off);
                #pragma unroll
                for (int j = 0; j < 2; ++j) lds_v2u64(nwlo[j], nwhi[j], waddr[j] + off);
            }
            #pragma unroll
            for (int j = 0; j < 2; ++j)
                #pragma unroll
                for (int i = 0; i < 4; ++i) {
                    acc[j][i] = fma2(chlo[i], cwlo[j], acc[j][i]);
                    acc[j][i] = fma2(chhi[i], cwhi[j], acc[j][i]);
                }
            if (kc < 15) {
                #pragma unroll
                for (int i = 0; i < 4; ++i) { chlo[i] = nhlo[i]; chhi[i] = nhhi[i]; }
                #pragma unroll
                for (int j = 0; j < 2; ++j) { cwlo[j] = nwlo[j]; cwhi[j] = nwhi[j]; }
            }
        }

        // gates -> gbuf (bank = 8*bl + rg + (16*warp + 8j) : 32 distinct per STS)
        #pragma unroll
        for (int j = 0; j < 2; ++j) {
            int r = warp * 16 + rg + 8 * j;
            #pragma unroll
            for (int i = 0; i < 4; ++i) {
                float lo, hi; unpack2(acc[j][i], lo, hi);
                gbuf[(bl + 4 * i) * GP + r] = lo + hi;
            }
        }
        __syncthreads();                        // bar1: gates visible

        // ---- update phase: warp = batch `warp`, units lane & lane+32 ----
        // PyTorch gate order i,f,g,o at offsets 0,64,128,192
        const float* gb = gbuf + warp * GP;
        float gi0 = gb[lane],       gf0 = gb[lane + 64];
        float gg0 = gb[lane + 128], go0 = gb[lane + 192];
        float gi1 = gb[lane + 32],  gf1 = gb[lane + 96];
        float gg1 = gb[lane + 160], go1 = gb[lane + 224];

        float iv0 = sigm(gi0), fv0 = sigm(gf0);
        float gv0 = tanh_mufu(gg0), ov0 = sigm(go0);
        c0 = fmaf(fv0, c0, iv0 * gv0);
        float hv0 = ov0 * tanh_mufu(c0);

        float iv1 = sigm(gi1), fv1 = sigm(gf1);
        float gv1 = tanh_mufu(gg1), ov1 = sigm(go1);
        c1 = fmaf(fv1, c1, iv1 * gv1);
        float hv1 = ov1 * tanh_mufu(c1);

        h_sh[warp * HP + lane]      = hv0;
        h_sh[warp * HP + lane + 32] = hv1;

        // ---- output head: out[b][t] = h . w_fc + b_fc (full-warp reduce) ----
        float po = fmaf(hv0, wfc0, hv1 * wfc1);
        #pragma unroll
        for (int off = 16; off > 0; off >>= 1)
            po += __shfl_xor_sync(0xffffffffu, po, off);
        if (lane == 0) out[(size_t)(b0 + warp) * T_LEN + t] = po + bfc;

        // stage next x chunk (writes after bar1; visible after bar2)
        if (tt == 63 && t + 1 < T_LEN) {
            #pragma unroll
            for (int q = 0; q < 2; ++q) {
                int idx = tid + 512 * q;
                int b = idx >> 6, t2 = idx & 63;
                x_sh[b * XP + t2] = x[(size_t)(b0 + b) * T_LEN + (t + 1) + t2];
            }
        }
        __syncthreads();                        // bar2: h + x visible for next step
    }
}

extern "C" void kernel_launch(void* const* d_in, const int* in_sizes, int n_in,
                              void* d_out, int out_size)
{
    const float* x    = (const float*)d_in[0];
    const float* w_ih = (const float*)d_in[1];
    const float* w_hh = (const float*)d_in[2];
    const float* b_ih = (const float*)d_in[3];
    const float* b_hh = (const float*)d_in[4];
    const float* w_fc = (const float*)d_in[5];
    const float* b_fc = (const float*)d_in[6];
    float* out = (float*)d_out;

    size_t smem = (size_t)(NGATE * WP + NB * HP + NB * GP + NB * XP) * sizeof(float);
    cudaFuncSetAttribute(lstm_kernel,
                         cudaFuncAttributeMaxDynamicSharedMemorySize, (int)smem);
    lstm_kernel<<<BATCH / NB, THREADS, smem>>>(x, w_ih, w_hh, b_ih, b_hh,
                                               w_fc, b_fc, out);
}